// round 6
// baseline (speedup 1.0000x reference)
#include <cuda_runtime.h>
#include <cuda_fp16.h>
#include <cstdint>
#include <cstddef>

// Problem constants
#define Bsz 4
#define Lsz 512
#define Dsz 768
#define Wsz 12
#define Ksz (Lsz * Wsz)
#define NTOK (Bsz * Ksz)     // 24576
#define BLROWS (Bsz * Lsz)   // 2048
#define FFD 3072
#define CATD 1536

// fp16 weight buffer offsets (elements). W1=[ws1;we1](6144,768),
// W2A=ws2(768,3072), W2B=we2(768,3072), W3=wo1(3072,1536), W4=wo2(768,3072)
#define OFF_W1A 0u
#define OFF_W1B 2359296u
#define OFF_W2A 4718592u
#define OFF_W2B 7077888u
#define OFF_W3  9437184u
#define OFF_W4  14155776u
#define WTOT    16515072u

// Static device scratch (allocation-free rule)
__device__ __half g_wh[WTOT];
__device__ __half g_h_hi[(size_t)BLROWS * Dsz];
__device__ __half g_h_lo[(size_t)BLROWS * Dsz];
__device__ __half g_hid_hi[(size_t)NTOK * FFD];   // L1 out lives here (2048x6144)
__device__ __half g_hid_lo[(size_t)NTOK * FFD];
__device__ __half g_cat_hi[(size_t)NTOK * CATD];
__device__ __half g_cat_lo[(size_t)NTOK * CATD];
__device__ float  g_se[(size_t)BLROWS * CATD];    // [start|end] reps, fp32
__device__ int    g_is64;

// ---------------------------------------------------------------------------
// span_idx dtype detection (int64 vs int32)
// ---------------------------------------------------------------------------
__global__ void detect_idx_kernel(const unsigned int* __restrict__ sp, int nhalf) {
    __shared__ int s_any;
    if (threadIdx.x == 0) s_any = 0;
    __syncthreads();
    int found = 0;
    for (int i = threadIdx.x; i < nhalf; i += blockDim.x)
        if (sp[2 * i + 1] != 0u) found = 1;
    if (found) atomicOr(&s_any, 1);
    __syncthreads();
    if (threadIdx.x == 0) g_is64 = (s_any == 0) ? 1 : 0;
}

// ---------------------------------------------------------------------------
// fp32 -> exact fp16 (hi, lo) split (A operands)
// ---------------------------------------------------------------------------
__global__ void splitA_kernel(const float* __restrict__ x,
                              __half* __restrict__ hi,
                              __half* __restrict__ lo, int n4)
{
    int t = blockIdx.x * blockDim.x + threadIdx.x;
    if (t >= n4) return;
    float4 v = ((const float4*)x)[t];
    __half h0 = __float2half_rn(v.x), h1 = __float2half_rn(v.y);
    __half h2 = __float2half_rn(v.z), h3 = __float2half_rn(v.w);
    __half l0 = __float2half_rn(v.x - __half2float(h0));
    __half l1 = __float2half_rn(v.y - __half2float(h1));
    __half l2 = __float2half_rn(v.z - __half2float(h2));
    __half l3 = __float2half_rn(v.w - __half2float(h3));
    __half hh[4] = {h0, h1, h2, h3};
    __half ll[4] = {l0, l1, l2, l3};
    ((uint2*)hi)[t] = *(uint2*)hh;
    ((uint2*)lo)[t] = *(uint2*)ll;
}

// fp32 -> fp16 single rounding (B / weight operands)
__global__ void convB_kernel(const float* __restrict__ x,
                             __half* __restrict__ h, int n4)
{
    int t = blockIdx.x * blockDim.x + threadIdx.x;
    if (t >= n4) return;
    float4 v = ((const float4*)x)[t];
    __half hh[4] = {__float2half_rn(v.x), __float2half_rn(v.y),
                    __float2half_rn(v.z), __float2half_rn(v.w)};
    ((uint2*)h)[t] = *(uint2*)hh;
}

// ---------------------------------------------------------------------------
// PTX helpers
// ---------------------------------------------------------------------------
__device__ __forceinline__ uint32_t smem_u32(const void* p) {
    return (uint32_t)__cvta_generic_to_shared(p);
}
__device__ __forceinline__ void ldm_x4(uint32_t* r, uint32_t addr) {
    asm volatile("ldmatrix.sync.aligned.m8n8.x4.shared.b16 {%0,%1,%2,%3}, [%4];"
                 : "=r"(r[0]), "=r"(r[1]), "=r"(r[2]), "=r"(r[3]) : "r"(addr));
}
__device__ __forceinline__ void ldm_x2(uint32_t* r, uint32_t addr) {
    asm volatile("ldmatrix.sync.aligned.m8n8.x2.shared.b16 {%0,%1}, [%2];"
                 : "=r"(r[0]), "=r"(r[1]) : "r"(addr));
}
__device__ __forceinline__ void mma_f16(float* d, const uint32_t* a, const uint32_t* b) {
    asm volatile(
        "mma.sync.aligned.m16n8k16.row.col.f32.f16.f16.f32 "
        "{%0,%1,%2,%3},{%4,%5,%6,%7},{%8,%9},{%0,%1,%2,%3};"
        : "+f"(d[0]), "+f"(d[1]), "+f"(d[2]), "+f"(d[3])
        : "r"(a[0]), "r"(a[1]), "r"(a[2]), "r"(a[3]), "r"(b[0]), "r"(b[1]));
}
__device__ __forceinline__ void cp16(uint32_t dst, const void* src) {
    asm volatile("cp.async.cg.shared.global [%0], [%1], 16;" :: "r"(dst), "l"(src));
}

// ---------------------------------------------------------------------------
// 2-pass split-fp16 tensor GEMM (NT): C = (Ah+Al)*Bh^T + bias, opt ReLU.
// A rows have stride lda (sub-matrix support); B rows stride K; C rows ldc.
// Block 128x128x32, cp.async double buffer, 8 warps (2x4), warp 64x32.
// Bias: bias1 for out-col < nsplit else bias2[col-nsplit].
// mode 0: fp32 C. mode 1: relu + exact fp16 hi/lo split C.
// Requires M%128==0, N%128==0, K%32==0.
// ---------------------------------------------------------------------------
#define SKB     80                 // bytes per smem row (32 fp16 + pad)
#define TILE_B  (128 * SKB)        // 10240
#define STAGE_B (3 * TILE_B)       // 30720 (Ah, Al, Bh)
#define SMEM_DYN (2 * STAGE_B)     // 61440

__global__ __launch_bounds__(256, 2)
void gemm2p_kernel(const __half* __restrict__ Ah,
                   const __half* __restrict__ Al,
                   const __half* __restrict__ Bh,
                   const float* __restrict__ bias1,
                   const float* __restrict__ bias2, int nsplit,
                   float* __restrict__ Cf,
                   __half* __restrict__ Ch,
                   __half* __restrict__ Cl,
                   int N, int K, int lda, int ldc, int mode)
{
    extern __shared__ char smem[];
    const uint32_t sbase = smem_u32(smem);

    const int tid  = threadIdx.x;
    const int lane = tid & 31;
    const int wid  = tid >> 5;
    const int wm   = (wid >> 2) * 64;
    const int wn   = (wid & 3) * 32;
    const int bm   = blockIdx.y << 7;
    const int bn   = blockIdx.x << 7;

    float acc[4][4][4];
#pragma unroll
    for (int i = 0; i < 4; i++)
#pragma unroll
        for (int j = 0; j < 4; j++)
#pragma unroll
            for (int r = 0; r < 4; r++) acc[i][j][r] = 0.f;

    const int crow = tid >> 2;
    const int cchk = (tid & 3) * 8;                      // fp16 elems
    const uint32_t drow = (uint32_t)crow * SKB + (tid & 3) * 16;

    const __half* aSrcH = Ah + (size_t)bm * lda;
    const __half* aSrcL = Al + (size_t)bm * lda;
    const __half* bSrc  = Bh + (size_t)bn * K;

    const int nk = K >> 5;

    auto issue = [&](int kt) {
        const int s = kt & 1;
        const int kb = kt << 5;
        uint32_t d0 = sbase + s * STAGE_B + drow;
#pragma unroll
        for (int half = 0; half < 2; half++) {
            const int r = half * 64 + crow;
            uint32_t dh = d0 + half * (64 * SKB);
            cp16(dh,              aSrcH + (size_t)r * lda + kb + cchk);
            cp16(dh + TILE_B,     aSrcL + (size_t)r * lda + kb + cchk);
            cp16(dh + 2 * TILE_B, bSrc  + (size_t)r * K   + kb + cchk);
        }
    };

    // ldmatrix lane mapping
    const int aq   = lane >> 3;
    const int arow = ((aq & 1) << 3) + (lane & 7);
    const int acol = (aq >> 1) << 3;
    const int brow = lane & 7;
    const int bcol = ((lane >> 3) & 1) << 3;

    issue(0);
    asm volatile("cp.async.commit_group;" ::: "memory");

    for (int kt = 0; kt < nk; kt++) {
        asm volatile("cp.async.wait_group 0;" ::: "memory");
        __syncthreads();
        if (kt + 1 < nk) issue(kt + 1);
        asm volatile("cp.async.commit_group;" ::: "memory");

        const uint32_t st  = sbase + (kt & 1) * STAGE_B;
        const uint32_t sAh = st;
        const uint32_t sAl = st + TILE_B;
        const uint32_t sBh = st + 2 * TILE_B;

#pragma unroll
        for (int kk = 0; kk < 32; kk += 16) {
            uint32_t a[4][4], b[4][2];
#pragma unroll
            for (int ni = 0; ni < 4; ni++) {
                uint32_t off = (uint32_t)(wn + ni * 8 + brow) * SKB + (kk + bcol) * 2;
                ldm_x2(b[ni], sBh + off);
            }
            // pass 1: Ah * Bh
#pragma unroll
            for (int mi = 0; mi < 4; mi++) {
                uint32_t off = (uint32_t)(wm + mi * 16 + arow) * SKB + (kk + acol) * 2;
                ldm_x4(a[mi], sAh + off);
            }
#pragma unroll
            for (int mi = 0; mi < 4; mi++)
#pragma unroll
                for (int ni = 0; ni < 4; ni++)
                    mma_f16(acc[mi][ni], a[mi], b[ni]);
            // pass 2: Al * Bh (reuse fragment regs)
#pragma unroll
            for (int mi = 0; mi < 4; mi++) {
                uint32_t off = (uint32_t)(wm + mi * 16 + arow) * SKB + (kk + acol) * 2;
                ldm_x4(a[mi], sAl + off);
            }
#pragma unroll
            for (int mi = 0; mi < 4; mi++)
#pragma unroll
                for (int ni = 0; ni < 4; ni++)
                    mma_f16(acc[mi][ni], a[mi], b[ni]);
        }
    }

    // Epilogue
    const int lr = lane >> 2;
    const int lc = (lane & 3) * 2;
#pragma unroll
    for (int mi = 0; mi < 4; mi++) {
#pragma unroll
        for (int ni = 0; ni < 4; ni++) {
            const int gm = bm + wm + mi * 16 + lr;
            const int gc = bn + wn + ni * 8 + lc;
            const float b0 = (gc < nsplit)     ? bias1[gc]     : bias2[gc - nsplit];
            const float b1 = (gc + 1 < nsplit) ? bias1[gc + 1] : bias2[gc + 1 - nsplit];
            float v0 = acc[mi][ni][0] + b0;
            float v1 = acc[mi][ni][1] + b1;
            float v2 = acc[mi][ni][2] + b0;
            float v3 = acc[mi][ni][3] + b1;
            if (mode == 0) {
                *(float2*)(Cf + (size_t)gm * ldc + gc)       = make_float2(v0, v1);
                *(float2*)(Cf + (size_t)(gm + 8) * ldc + gc) = make_float2(v2, v3);
            } else {
                v0 = fmaxf(v0, 0.f); v1 = fmaxf(v1, 0.f);
                v2 = fmaxf(v2, 0.f); v3 = fmaxf(v3, 0.f);
                __half h0 = __float2half_rn(v0), h1 = __float2half_rn(v1);
                __half h2 = __float2half_rn(v2), h3 = __float2half_rn(v3);
                __half l0 = __float2half_rn(v0 - __half2float(h0));
                __half l1 = __float2half_rn(v1 - __half2float(h1));
                __half l2 = __float2half_rn(v2 - __half2float(h2));
                __half l3 = __float2half_rn(v3 - __half2float(h3));
                __half p01[2] = {h0, h1}, p23[2] = {h2, h3};
                __half q01[2] = {l0, l1}, q23[2] = {l2, l3};
                *(uint32_t*)(Ch + (size_t)gm * ldc + gc)       = *(uint32_t*)p01;
                *(uint32_t*)(Cl + (size_t)gm * ldc + gc)       = *(uint32_t*)q01;
                *(uint32_t*)(Ch + (size_t)(gm + 8) * ldc + gc) = *(uint32_t*)p23;
                *(uint32_t*)(Cl + (size_t)(gm + 8) * ldc + gc) = *(uint32_t*)q23;
            }
        }
    }
}

// ---------------------------------------------------------------------------
// Gather spans from combined se[2048,1536] (cols 0-767 start, 768-1535 end),
// ReLU, exact fp16 split -> cat_hi/cat_lo [NTOK, 1536]
// ---------------------------------------------------------------------------
__global__ void gather_cat_kernel(const float* __restrict__ se,
                                  const void* __restrict__ span,
                                  __half* __restrict__ cat_hi,
                                  __half* __restrict__ cat_lo)
{
    const int QD = CATD / 4;
    int t = blockIdx.x * blockDim.x + threadIdx.x;
    if (t >= NTOK * QD) return;
    int r = t / QD;
    int q = t - r * QD;
    int b = r / Ksz;
    int col = q * 4;

    int which = (col < Dsz) ? 0 : 1;
    size_t pos = (size_t)r * 2 + which;
    long long idx;
    if (g_is64) idx = ((const long long*)span)[pos];
    else        idx = (long long)((const int*)span)[pos];

    const float* src = se + ((size_t)b * Lsz + idx) * CATD + col;

    float4 v = *(const float4*)src;
    v.x = fmaxf(v.x, 0.f); v.y = fmaxf(v.y, 0.f);
    v.z = fmaxf(v.z, 0.f); v.w = fmaxf(v.w, 0.f);

    __half h0 = __float2half_rn(v.x), h1 = __float2half_rn(v.y);
    __half h2 = __float2half_rn(v.z), h3 = __float2half_rn(v.w);
    __half l0 = __float2half_rn(v.x - __half2float(h0));
    __half l1 = __float2half_rn(v.y - __half2float(h1));
    __half l2 = __float2half_rn(v.z - __half2float(h2));
    __half l3 = __float2half_rn(v.w - __half2float(h3));
    __half hh[4] = {h0, h1, h2, h3};
    __half ll[4] = {l0, l1, l2, l3};
    ((uint2*)cat_hi)[t] = *(uint2*)hh;
    ((uint2*)cat_lo)[t] = *(uint2*)ll;
}

// ---------------------------------------------------------------------------
// Launch
// ---------------------------------------------------------------------------
extern "C" void kernel_launch(void* const* d_in, const int* in_sizes, int n_in,
                              void* d_out, int out_size)
{
    const float* h   = (const float*)d_in[0];
    const void*  sp  = d_in[1];
    const float* ws1 = (const float*)d_in[2];
    const float* bs1 = (const float*)d_in[3];
    const float* ws2 = (const float*)d_in[4];
    const float* bs2 = (const float*)d_in[5];
    const float* we1 = (const float*)d_in[6];
    const float* be1 = (const float*)d_in[7];
    const float* we2 = (const float*)d_in[8];
    const float* be2 = (const float*)d_in[9];
    const float* wo1 = (const float*)d_in[10];
    const float* bo1 = (const float*)d_in[11];
    const float* wo2 = (const float*)d_in[12];
    const float* bo2 = (const float*)d_in[13];
    float* out = (float*)d_out;

    __half *wh, *hhi, *hlo, *dhhi, *dhlo, *chi, *clo;
    float *se;
    cudaGetSymbolAddress((void**)&wh,   g_wh);
    cudaGetSymbolAddress((void**)&hhi,  g_h_hi);
    cudaGetSymbolAddress((void**)&hlo,  g_h_lo);
    cudaGetSymbolAddress((void**)&dhhi, g_hid_hi);
    cudaGetSymbolAddress((void**)&dhlo, g_hid_lo);
    cudaGetSymbolAddress((void**)&chi,  g_cat_hi);
    cudaGetSymbolAddress((void**)&clo,  g_cat_lo);
    cudaGetSymbolAddress((void**)&se,   g_se);

    cudaFuncSetAttribute(gemm2p_kernel,
                         cudaFuncAttributeMaxDynamicSharedMemorySize, SMEM_DYN);

    detect_idx_kernel<<<1, 256>>>((const unsigned int*)sp, NTOK);

    // Precision prep: h exact-split; weights single-rounded fp16
    {
        int n4 = (BLROWS * Dsz) / 4;
        splitA_kernel<<<(n4 + 255) / 256, 256>>>(h, hhi, hlo, n4);
        n4 = (FFD * Dsz) / 4;
        convB_kernel<<<(n4 + 255) / 256, 256>>>(ws1, wh + OFF_W1A, n4);
        convB_kernel<<<(n4 + 255) / 256, 256>>>(we1, wh + OFF_W1B, n4);
        n4 = (Dsz * FFD) / 4;
        convB_kernel<<<(n4 + 255) / 256, 256>>>(ws2, wh + OFF_W2A, n4);
        convB_kernel<<<(n4 + 255) / 256, 256>>>(we2, wh + OFF_W2B, n4);
        n4 = (FFD * CATD) / 4;
        convB_kernel<<<(n4 + 255) / 256, 256>>>(wo1, wh + OFF_W3, n4);
        n4 = (Dsz * FFD) / 4;
        convB_kernel<<<(n4 + 255) / 256, 256>>>(wo2, wh + OFF_W4, n4);
    }

    // L1 fused start|end layer1: hid[2048, 6144] = h @ [ws1;we1]^T, relu, split
    // (valid fusion: same A for all output columns)
    gemm2p_kernel<<<dim3(6144/128, BLROWS/128), 256, SMEM_DYN>>>(
        hhi, hlo, wh + OFF_W1A, bs1, be1, FFD, nullptr, dhhi, dhlo,
        6144, Dsz, Dsz, 6144, 1);

    // L2 start: se[:, 0:768] = hid[:, 0:3072] @ ws2^T  (lda=6144, ldc=1536)
    gemm2p_kernel<<<dim3(Dsz/128, BLROWS/128), 256, SMEM_DYN>>>(
        dhhi, dhlo, wh + OFF_W2A, bs2, bs2, Dsz, se, nullptr, nullptr,
        Dsz, FFD, 6144, CATD, 0);
    // L2 end:   se[:, 768:1536] = hid[:, 3072:6144] @ we2^T
    gemm2p_kernel<<<dim3(Dsz/128, BLROWS/128), 256, SMEM_DYN>>>(
        dhhi + FFD, dhlo + FFD, wh + OFF_W2B, be2, be2, Dsz, se + Dsz, nullptr, nullptr,
        Dsz, FFD, 6144, CATD, 0);

    // gather + concat + relu + split
    int gthreads = NTOK * (CATD / 4);
    gather_cat_kernel<<<(gthreads + 255) / 256, 256>>>(se, sp, chi, clo);

    // L3: hid[24576, 3072] = cat @ wo1^T, relu, split
    gemm2p_kernel<<<dim3(FFD/128, NTOK/128), 256, SMEM_DYN>>>(
        chi, clo, wh + OFF_W3, bo1, bo1, FFD, nullptr, dhhi, dhlo,
        FFD, CATD, CATD, FFD, 1);

    // L4: out[24576, 768] = hid @ wo2^T (fp32)
    gemm2p_kernel<<<dim3(Dsz/128, NTOK/128), 256, SMEM_DYN>>>(
        dhhi, dhlo, wh + OFF_W4, bo2, bo2, Dsz, out, nullptr, nullptr,
        Dsz, FFD, FFD, Dsz, 0);
}

// round 7
// speedup vs baseline: 1.4876x; 1.4876x over previous
#include <cuda_runtime.h>
#include <cuda_fp16.h>
#include <cstdint>
#include <cstddef>

// Problem constants
#define Bsz 4
#define Lsz 512
#define Dsz 768
#define Wsz 12
#define Ksz (Lsz * Wsz)
#define NTOK (Bsz * Ksz)     // 24576
#define BLROWS (Bsz * Lsz)   // 2048
#define FFD 3072
#define CATD 1536

// fp16 weight buffer offsets (elements)
#define OFF_W1A 0u
#define OFF_W1B 2359296u
#define OFF_W2A 4718592u
#define OFF_W2B 7077888u
#define OFF_W3  9437184u
#define OFF_W4  14155776u
#define WTOT    16515072u

// Static device scratch (allocation-free rule)
__device__ alignas(128) __half g_wh[WTOT];
__device__ alignas(128) __half g_h_hi[(size_t)BLROWS * Dsz];
__device__ alignas(128) __half g_h_lo[(size_t)BLROWS * Dsz];
__device__ alignas(128) __half g_hid_hi[(size_t)NTOK * FFD];
__device__ alignas(128) __half g_hid_lo[(size_t)NTOK * FFD];
__device__ alignas(128) __half g_cat_hi[(size_t)NTOK * CATD];
__device__ alignas(128) __half g_cat_lo[(size_t)NTOK * CATD];
__device__ alignas(128) float  g_se[(size_t)BLROWS * CATD];
__device__ int g_is64;

// ---------------------------------------------------------------------------
// span_idx dtype detection (int64 vs int32)
// ---------------------------------------------------------------------------
__global__ void detect_idx_kernel(const unsigned int* __restrict__ sp, int nhalf) {
    __shared__ int s_any;
    if (threadIdx.x == 0) s_any = 0;
    __syncthreads();
    int found = 0;
    for (int i = threadIdx.x; i < nhalf; i += blockDim.x)
        if (sp[2 * i + 1] != 0u) found = 1;
    if (found) atomicOr(&s_any, 1);
    __syncthreads();
    if (threadIdx.x == 0) g_is64 = (s_any == 0) ? 1 : 0;
}

// ---------------------------------------------------------------------------
// fp32 -> exact fp16 (hi, lo) split (A operands)
// ---------------------------------------------------------------------------
__global__ void splitA_kernel(const float* __restrict__ x,
                              __half* __restrict__ hi,
                              __half* __restrict__ lo, int n4)
{
    int t = blockIdx.x * blockDim.x + threadIdx.x;
    if (t >= n4) return;
    float4 v = ((const float4*)x)[t];
    __half h0 = __float2half_rn(v.x), h1 = __float2half_rn(v.y);
    __half h2 = __float2half_rn(v.z), h3 = __float2half_rn(v.w);
    __half l0 = __float2half_rn(v.x - __half2float(h0));
    __half l1 = __float2half_rn(v.y - __half2float(h1));
    __half l2 = __float2half_rn(v.z - __half2float(h2));
    __half l3 = __float2half_rn(v.w - __half2float(h3));
    __half hh[4] = {h0, h1, h2, h3};
    __half ll[4] = {l0, l1, l2, l3};
    ((uint2*)hi)[t] = *(uint2*)hh;
    ((uint2*)lo)[t] = *(uint2*)ll;
}

// fp32 -> fp16 single rounding (B / weight operands)
__global__ void convB_kernel(const float* __restrict__ x,
                             __half* __restrict__ h, int n4)
{
    int t = blockIdx.x * blockDim.x + threadIdx.x;
    if (t >= n4) return;
    float4 v = ((const float4*)x)[t];
    __half hh[4] = {__float2half_rn(v.x), __float2half_rn(v.y),
                    __float2half_rn(v.z), __float2half_rn(v.w)};
    ((uint2*)h)[t] = *(uint2*)hh;
}

// ---------------------------------------------------------------------------
// PTX helpers
// ---------------------------------------------------------------------------
__device__ __forceinline__ uint32_t smem_u32(const void* p) {
    return (uint32_t)__cvta_generic_to_shared(p);
}
__device__ __forceinline__ void ldm_x4(uint32_t* r, uint32_t addr) {
    asm volatile("ldmatrix.sync.aligned.m8n8.x4.shared.b16 {%0,%1,%2,%3}, [%4];"
                 : "=r"(r[0]), "=r"(r[1]), "=r"(r[2]), "=r"(r[3]) : "r"(addr));
}
__device__ __forceinline__ void mma_f16(float* d, const uint32_t* a, const uint32_t* b) {
    asm volatile(
        "mma.sync.aligned.m16n8k16.row.col.f32.f16.f16.f32 "
        "{%0,%1,%2,%3},{%4,%5,%6,%7},{%8,%9},{%0,%1,%2,%3};"
        : "+f"(d[0]), "+f"(d[1]), "+f"(d[2]), "+f"(d[3])
        : "r"(a[0]), "r"(a[1]), "r"(a[2]), "r"(a[3]), "r"(b[0]), "r"(b[1]));
}
__device__ __forceinline__ void cp16(uint32_t dst, const void* src) {
    asm volatile("cp.async.cg.shared.global [%0], [%1], 16;" :: "r"(dst), "l"(src));
}

// ---------------------------------------------------------------------------
// 2-pass split-fp16 tensor GEMM (NT): C = (Ah+Al)*Bh^T + bias, opt ReLU.
// Block 128x128x64, cp.async 2-stage, fragment double-buffer, 8 warps (2x4),
// warp tile 64x32. A row stride lda; B rows stride K; C rows ldc.
// Bias: bias1 for out-col < nsplit else bias2[col-nsplit].
// mode 0: fp32 C. mode 1: relu + exact fp16 hi/lo split C.
// Requires M%128==0, N%128==0, K%64==0.
// ---------------------------------------------------------------------------
#define BK      64
#define SKB     144                // bytes per smem row (128B data + 16B pad)
#define TILE_B  (128 * SKB)        // 18432
#define STAGE_B (3 * TILE_B)       // 55296 (Ah, Al, Bh)
#define SMEM_DYN (2 * STAGE_B)     // 110592

__global__ __launch_bounds__(256, 1)
void gemm2p_kernel(const __half* __restrict__ Ah,
                   const __half* __restrict__ Al,
                   const __half* __restrict__ Bh,
                   const float* __restrict__ bias1,
                   const float* __restrict__ bias2, int nsplit,
                   float* __restrict__ Cf,
                   __half* __restrict__ Ch,
                   __half* __restrict__ Cl,
                   int N, int K, int lda, int ldc, int mode)
{
    extern __shared__ char smem[];
    const uint32_t sbase = smem_u32(smem);

    const int tid  = threadIdx.x;
    const int lane = tid & 31;
    const int wid  = tid >> 5;
    const int wm   = (wid >> 2) * 64;
    const int wn   = (wid & 3) * 32;
    const int bm   = blockIdx.y << 7;
    const int bn   = blockIdx.x << 7;

    float acc[4][4][4];
#pragma unroll
    for (int i = 0; i < 4; i++)
#pragma unroll
        for (int j = 0; j < 4; j++)
#pragma unroll
            for (int r = 0; r < 4; r++) acc[i][j][r] = 0.f;

    const __half* aSrcH = Ah + (size_t)bm * lda;
    const __half* aSrcL = Al + (size_t)bm * lda;
    const __half* bSrc  = Bh + (size_t)bn * K;

    const int nk = K / BK;

    // cp.async: per tile 128 rows x 8 chunks(16B) = 1024 chunks, 4/thread
    auto issue = [&](int kt) {
        const int s = kt & 1;
        const int kb = kt * BK;
        const uint32_t st = sbase + s * STAGE_B;
#pragma unroll
        for (int i = 0; i < 4; i++) {
            const int c   = tid + 256 * i;
            const int row = c >> 3;
            const int ch  = c & 7;
            const uint32_t doff = (uint32_t)row * SKB + ch * 16;
            cp16(st + doff,              aSrcH + (size_t)row * lda + kb + ch * 8);
            cp16(st + TILE_B + doff,     aSrcL + (size_t)row * lda + kb + ch * 8);
            cp16(st + 2 * TILE_B + doff, bSrc  + (size_t)row * K   + kb + ch * 8);
        }
    };

    // ldmatrix lane mapping (A: m16k16 x4; B: 2 n-frags per x4)
    const int aq    = lane >> 3;
    const int arow  = ((aq & 1) << 3) + (lane & 7);
    const int acol  = (aq >> 1) << 3;
    const int brow4 = ((lane >> 4) << 3) + (lane & 7);
    const int bcol4 = ((lane >> 3) & 1) << 3;

    uint32_t aH[2][4][4], aL[2][4][4], bb[2][2][4];

    auto ldfrag = [&](uint32_t st, int kk, int fb) {
        const uint32_t sAh = st;
        const uint32_t sAl = st + TILE_B;
        const uint32_t sB  = st + 2 * TILE_B;
#pragma unroll
        for (int mi = 0; mi < 4; mi++) {
            const uint32_t off = (uint32_t)(wm + mi * 16 + arow) * SKB + (kk + acol) * 2;
            ldm_x4(aH[fb][mi], sAh + off);
            ldm_x4(aL[fb][mi], sAl + off);
        }
#pragma unroll
        for (int p = 0; p < 2; p++) {
            const uint32_t off = (uint32_t)(wn + p * 16 + brow4) * SKB + (kk + bcol4) * 2;
            ldm_x4(bb[fb][p], sB + off);
        }
    };

    issue(0);
    asm volatile("cp.async.commit_group;" ::: "memory");

    for (int kt = 0; kt < nk; kt++) {
        asm volatile("cp.async.wait_group 0;" ::: "memory");
        __syncthreads();
        if (kt + 1 < nk) issue(kt + 1);
        asm volatile("cp.async.commit_group;" ::: "memory");

        const uint32_t st = sbase + (kt & 1) * STAGE_B;

        ldfrag(st, 0, 0);
#pragma unroll
        for (int j = 0; j < 4; j++) {
            const int cur = j & 1;
            if (j < 3) ldfrag(st, (j + 1) * 16, cur ^ 1);
            // 32 back-to-back MMAs on current fragment buffer
#pragma unroll
            for (int mi = 0; mi < 4; mi++)
#pragma unroll
                for (int p = 0; p < 2; p++) {
                    mma_f16(acc[mi][2 * p],     aH[cur][mi], &bb[cur][p][0]);
                    mma_f16(acc[mi][2 * p + 1], aH[cur][mi], &bb[cur][p][2]);
                }
#pragma unroll
            for (int mi = 0; mi < 4; mi++)
#pragma unroll
                for (int p = 0; p < 2; p++) {
                    mma_f16(acc[mi][2 * p],     aL[cur][mi], &bb[cur][p][0]);
                    mma_f16(acc[mi][2 * p + 1], aL[cur][mi], &bb[cur][p][2]);
                }
        }
    }

    // Epilogue
    const int lr = lane >> 2;
    const int lc = (lane & 3) * 2;
#pragma unroll
    for (int mi = 0; mi < 4; mi++) {
#pragma unroll
        for (int ni = 0; ni < 4; ni++) {
            const int gm = bm + wm + mi * 16 + lr;
            const int gc = bn + wn + ni * 8 + lc;
            const float b0 = (gc < nsplit)     ? bias1[gc]     : bias2[gc - nsplit];
            const float b1 = (gc + 1 < nsplit) ? bias1[gc + 1] : bias2[gc + 1 - nsplit];
            float v0 = acc[mi][ni][0] + b0;
            float v1 = acc[mi][ni][1] + b1;
            float v2 = acc[mi][ni][2] + b0;
            float v3 = acc[mi][ni][3] + b1;
            if (mode == 0) {
                *(float2*)(Cf + (size_t)gm * ldc + gc)       = make_float2(v0, v1);
                *(float2*)(Cf + (size_t)(gm + 8) * ldc + gc) = make_float2(v2, v3);
            } else {
                v0 = fmaxf(v0, 0.f); v1 = fmaxf(v1, 0.f);
                v2 = fmaxf(v2, 0.f); v3 = fmaxf(v3, 0.f);
                __half h0 = __float2half_rn(v0), h1 = __float2half_rn(v1);
                __half h2 = __float2half_rn(v2), h3 = __float2half_rn(v3);
                __half l0 = __float2half_rn(v0 - __half2float(h0));
                __half l1 = __float2half_rn(v1 - __half2float(h1));
                __half l2 = __float2half_rn(v2 - __half2float(h2));
                __half l3 = __float2half_rn(v3 - __half2float(h3));
                __half p01[2] = {h0, h1}, p23[2] = {h2, h3};
                __half q01[2] = {l0, l1}, q23[2] = {l2, l3};
                *(uint32_t*)(Ch + (size_t)gm * ldc + gc)       = *(uint32_t*)p01;
                *(uint32_t*)(Cl + (size_t)gm * ldc + gc)       = *(uint32_t*)q01;
                *(uint32_t*)(Ch + (size_t)(gm + 8) * ldc + gc) = *(uint32_t*)p23;
                *(uint32_t*)(Cl + (size_t)(gm + 8) * ldc + gc) = *(uint32_t*)q23;
            }
        }
    }
}

// ---------------------------------------------------------------------------
// Gather spans from combined se[2048,1536], ReLU, exact fp16 split
// ---------------------------------------------------------------------------
__global__ void gather_cat_kernel(const float* __restrict__ se,
                                  const void* __restrict__ span,
                                  __half* __restrict__ cat_hi,
                                  __half* __restrict__ cat_lo)
{
    const int QD = CATD / 4;
    int t = blockIdx.x * blockDim.x + threadIdx.x;
    if (t >= NTOK * QD) return;
    int r = t / QD;
    int q = t - r * QD;
    int b = r / Ksz;
    int col = q * 4;

    int which = (col < Dsz) ? 0 : 1;
    size_t pos = (size_t)r * 2 + which;
    long long idx;
    if (g_is64) idx = ((const long long*)span)[pos];
    else        idx = (long long)((const int*)span)[pos];

    const float* src = se + ((size_t)b * Lsz + idx) * CATD + col;

    float4 v = *(const float4*)src;
    v.x = fmaxf(v.x, 0.f); v.y = fmaxf(v.y, 0.f);
    v.z = fmaxf(v.z, 0.f); v.w = fmaxf(v.w, 0.f);

    __half h0 = __float2half_rn(v.x), h1 = __float2half_rn(v.y);
    __half h2 = __float2half_rn(v.z), h3 = __float2half_rn(v.w);
    __half l0 = __float2half_rn(v.x - __half2float(h0));
    __half l1 = __float2half_rn(v.y - __half2float(h1));
    __half l2 = __float2half_rn(v.z - __half2float(h2));
    __half l3 = __float2half_rn(v.w - __half2float(h3));
    __half hh[4] = {h0, h1, h2, h3};
    __half ll[4] = {l0, l1, l2, l3};
    ((uint2*)cat_hi)[t] = *(uint2*)hh;
    ((uint2*)cat_lo)[t] = *(uint2*)ll;
}

// ---------------------------------------------------------------------------
// Launch
// ---------------------------------------------------------------------------
extern "C" void kernel_launch(void* const* d_in, const int* in_sizes, int n_in,
                              void* d_out, int out_size)
{
    const float* h   = (const float*)d_in[0];
    const void*  sp  = d_in[1];
    const float* ws1 = (const float*)d_in[2];
    const float* bs1 = (const float*)d_in[3];
    const float* ws2 = (const float*)d_in[4];
    const float* bs2 = (const float*)d_in[5];
    const float* we1 = (const float*)d_in[6];
    const float* be1 = (const float*)d_in[7];
    const float* we2 = (const float*)d_in[8];
    const float* be2 = (const float*)d_in[9];
    const float* wo1 = (const float*)d_in[10];
    const float* bo1 = (const float*)d_in[11];
    const float* wo2 = (const float*)d_in[12];
    const float* bo2 = (const float*)d_in[13];
    float* out = (float*)d_out;

    __half *wh, *hhi, *hlo, *dhhi, *dhlo, *chi, *clo;
    float *se;
    cudaGetSymbolAddress((void**)&wh,   g_wh);
    cudaGetSymbolAddress((void**)&hhi,  g_h_hi);
    cudaGetSymbolAddress((void**)&hlo,  g_h_lo);
    cudaGetSymbolAddress((void**)&dhhi, g_hid_hi);
    cudaGetSymbolAddress((void**)&dhlo, g_hid_lo);
    cudaGetSymbolAddress((void**)&chi,  g_cat_hi);
    cudaGetSymbolAddress((void**)&clo,  g_cat_lo);
    cudaGetSymbolAddress((void**)&se,   g_se);

    cudaFuncSetAttribute(gemm2p_kernel,
                         cudaFuncAttributeMaxDynamicSharedMemorySize, SMEM_DYN);

    detect_idx_kernel<<<1, 256>>>((const unsigned int*)sp, NTOK);

    // Precision prep
    {
        int n4 = (BLROWS * Dsz) / 4;
        splitA_kernel<<<(n4 + 255) / 256, 256>>>(h, hhi, hlo, n4);
        n4 = (FFD * Dsz) / 4;
        convB_kernel<<<(n4 + 255) / 256, 256>>>(ws1, wh + OFF_W1A, n4);
        convB_kernel<<<(n4 + 255) / 256, 256>>>(we1, wh + OFF_W1B, n4);
        n4 = (Dsz * FFD) / 4;
        convB_kernel<<<(n4 + 255) / 256, 256>>>(ws2, wh + OFF_W2A, n4);
        convB_kernel<<<(n4 + 255) / 256, 256>>>(we2, wh + OFF_W2B, n4);
        n4 = (FFD * CATD) / 4;
        convB_kernel<<<(n4 + 255) / 256, 256>>>(wo1, wh + OFF_W3, n4);
        n4 = (Dsz * FFD) / 4;
        convB_kernel<<<(n4 + 255) / 256, 256>>>(wo2, wh + OFF_W4, n4);
    }

    // L1 fused start|end layer1: hid[2048, 6144] = h @ [ws1;we1]^T, relu, split
    gemm2p_kernel<<<dim3(6144/128, BLROWS/128), 256, SMEM_DYN>>>(
        hhi, hlo, wh + OFF_W1A, bs1, be1, FFD, nullptr, dhhi, dhlo,
        6144, Dsz, Dsz, 6144, 1);

    // L2 start: se[:, 0:768] = hid[:, 0:3072] @ ws2^T
    gemm2p_kernel<<<dim3(Dsz/128, BLROWS/128), 256, SMEM_DYN>>>(
        dhhi, dhlo, wh + OFF_W2A, bs2, bs2, Dsz, se, nullptr, nullptr,
        Dsz, FFD, 6144, CATD, 0);
    // L2 end: se[:, 768:1536] = hid[:, 3072:6144] @ we2^T
    gemm2p_kernel<<<dim3(Dsz/128, BLROWS/128), 256, SMEM_DYN>>>(
        dhhi + FFD, dhlo + FFD, wh + OFF_W2B, be2, be2, Dsz, se + Dsz, nullptr, nullptr,
        Dsz, FFD, 6144, CATD, 0);

    // gather + concat + relu + split
    int gthreads = NTOK * (CATD / 4);
    gather_cat_kernel<<<(gthreads + 255) / 256, 256>>>(se, sp, chi, clo);

    // L3: hid[24576, 3072] = cat @ wo1^T, relu, split
    gemm2p_kernel<<<dim3(FFD/128, NTOK/128), 256, SMEM_DYN>>>(
        chi, clo, wh + OFF_W3, bo1, bo1, FFD, nullptr, dhhi, dhlo,
        FFD, CATD, CATD, FFD, 1);

    // L4: out[24576, 768] = hid @ wo2^T (fp32)
    gemm2p_kernel<<<dim3(Dsz/128, NTOK/128), 256, SMEM_DYN>>>(
        dhhi, dhlo, wh + OFF_W4, bo2, bo2, Dsz, out, nullptr, nullptr,
        Dsz, FFD, FFD, Dsz, 0);
}